// round 3
// baseline (speedup 1.0000x reference)
#include <cuda_runtime.h>

// MultiScaleProcessor: images [64,256,256,3] f32 ->
// out [64, 4(scales 32/64/128/256), 256, 256, 3] f32.
// Per scale: bilinear resize (jnp.linspace(0, 255, s) sampling), centered
// zero-pad to 256x256.
//
// Grid: (64 row-groups of 4, 4 scales, 64 images), block = 192 threads.
// Each thread writes 4 float4 stores (one per row in the group) -> deep
// store MLP. All pad-region boundaries (112/144, 96/160, 64/192) are
// multiples of 4, so the pad/interior/copy branch is block-uniform.
// Output is write-once: __stcs streaming stores keep L2 for the input.

#define IMG_H 256
#define IMG_W 256
#define C 3
#define FLOATS_PER_ROW (IMG_W * C)                 // 768
#define VEC_PER_ROW (FLOATS_PER_ROW / 4)           // 192
#define FLOATS_PER_PLANE (IMG_H * FLOATS_PER_ROW)  // 196608
#define VEC_PER_PLANE (FLOATS_PER_PLANE / 4)       // 49152
#define RPB 4                                      // rows per block

__global__ __launch_bounds__(VEC_PER_ROW) void msp_kernel(const float* __restrict__ in,
                                                          float* __restrict__ out) {
    const int ybase = blockIdx.x * RPB;  // first output row of this block
    const int sidx  = blockIdx.y;        // 0:32 1:64 2:128 3:256
    const int b     = blockIdx.z;        // image
    const int vx    = threadIdx.x;       // float4 within row

    const float* __restrict__ img = in + (size_t)b * FLOATS_PER_PLANE;
    float4* __restrict__ oplane = reinterpret_cast<float4*>(out)
        + (size_t)(b * 4 + sidx) * VEC_PER_PLANE;

    if (sidx == 3) {
        // Native resolution: 4-row float4 copy, batched loads then stores.
        float4 v[RPB];
        #pragma unroll
        for (int r = 0; r < RPB; ++r)
            v[r] = reinterpret_cast<const float4*>(img)[(size_t)(ybase + r) * VEC_PER_ROW + vx];
        #pragma unroll
        for (int r = 0; r < RPB; ++r)
            __stcs(&oplane[(size_t)(ybase + r) * VEC_PER_ROW + vx], v[r]);
        return;
    }

    const int s = 32 << sidx;
    const int p = (IMG_H - s) >> 1;      // centered pad
    const int yi0 = ybase - p;

    if ((unsigned)yi0 >= (unsigned)s) {
        // All 4 rows are pad (boundaries are multiples of RPB): zero stream.
        const float4 z = make_float4(0.f, 0.f, 0.f, 0.f);
        #pragma unroll
        for (int r = 0; r < RPB; ++r)
            __stcs(&oplane[(size_t)(ybase + r) * VEC_PER_ROW + vx], z);
        return;
    }

    // Interior rows: bilinear sample, 4 rows per thread.
    const float step = 255.0f / (float)(s - 1);

    // x-side mapping depends only on vx -> hoist out of the row loop.
    int   i00[4], i01[4];
    float wxv[4];
    bool  valid[4];
    {
        int f = vx * 4;
        #pragma unroll
        for (int k = 0; k < 4; ++k, ++f) {
            const int xo = f / 3;                    // output pixel x
            const int c  = f - xo * 3;               // channel
            const int xi = xo - p;
            valid[k] = ((unsigned)xi < (unsigned)s);
            const float fx = valid[k] ? (float)xi * step : 0.0f;
            const int   x0 = (int)fx;
            wxv[k] = fx - (float)x0;
            const int x1 = min(x0 + 1, IMG_W - 1);
            i00[k] = x0 * C + c;
            i01[k] = x1 * C + c;
        }
    }

    #pragma unroll
    for (int r = 0; r < RPB; ++r) {
        const int yi = yi0 + r;
        const float fy = (float)yi * step;
        const int   y0 = (int)fy;
        const float wy = fy - (float)y0;
        const int   y1 = min(y0 + 1, IMG_H - 1);
        const float omy = 1.0f - wy;
        const float* __restrict__ row0 = img + y0 * FLOATS_PER_ROW;
        const float* __restrict__ row1 = img + y1 * FLOATS_PER_ROW;

        float res[4];
        #pragma unroll
        for (int k = 0; k < 4; ++k) {
            float val = 0.0f;
            if (valid[k]) {
                const float wx = wxv[k];
                const float omx = 1.0f - wx;
                const float top = row0[i00[k]] * omx + row0[i01[k]] * wx;
                const float bot = row1[i00[k]] * omx + row1[i01[k]] * wx;
                val = top * omy + bot * wy;
            }
            res[k] = val;
        }
        __stcs(&oplane[(size_t)(ybase + r) * VEC_PER_ROW + vx],
               make_float4(res[0], res[1], res[2], res[3]));
    }
}

extern "C" void kernel_launch(void* const* d_in, const int* in_sizes, int n_in,
                              void* d_out, int out_size) {
    const float* images = (const float*)d_in[0];
    float* out = (float*)d_out;
    dim3 grid(IMG_H / RPB, 4, 64);       // 64 x 4 x 64 = 16384 blocks
    dim3 block(VEC_PER_ROW);             // 192 threads
    msp_kernel<<<grid, block>>>(images, out);
}